// round 2
// baseline (speedup 1.0000x reference)
#include <cuda_runtime.h>

// ---------------------------------------------------------------------------
// Problem constants
// ---------------------------------------------------------------------------
#define B_SZ 2
#define S_SZ 2048
#define D_SZ 1024
#define H_SZ 16
#define DK_SZ 64
#define M_SZ (B_SZ * S_SZ)                    // 4096 rows
#define OUT_ELEMS (B_SZ * S_SZ * D_SZ)        // 4,194,304
#define ATTN_ELEMS (134217728)                // B*H*S*S = 2*16*2048*2048

// ---------------------------------------------------------------------------
// Scratch (static device globals; allocation inside kernel_launch is banned)
// ---------------------------------------------------------------------------
__device__ float g_q[M_SZ * D_SZ];     // [b,h,s,dk]
__device__ float g_k[M_SZ * D_SZ];     // [b,h,s,dk]
__device__ float g_v[M_SZ * D_SZ];     // [b,h,s,dv]
__device__ float g_ctx[M_SZ * D_SZ];   // [b,s, h*dv]
__device__ float g_o[M_SZ * D_SZ];     // [b,s, d]  (pre-residual / pre-LN)

// ---------------------------------------------------------------------------
// Tiled fp32 GEMM:  C = A[M,1024] @ W[1024,1024] + bias
//   mode 0: C row-major [M,1024]
//   mode 1: C written as [b, h, s, 64]   (projection layout for attention)
// 64x64 tile, 16x16 threads, 4x4 micro-tile, TK=16
// ---------------------------------------------------------------------------
__global__ void __launch_bounds__(256) gemm_kernel(
    const float* __restrict__ A, const float* __restrict__ W,
    const float* __restrict__ bias, float* __restrict__ C, int mode)
{
    __shared__ __align__(16) float As[16][68];   // padded rows
    __shared__ __align__(16) float Bs[16][68];

    const int tid = threadIdx.x;
    const int tx = tid & 15;
    const int ty = tid >> 4;
    const int m0 = blockIdx.y * 64;
    const int n0 = blockIdx.x * 64;

    float acc[4][4] = {};

    for (int k0 = 0; k0 < D_SZ; k0 += 16) {
        // Load A tile (64 rows x 16 k), stored transposed As[k][m]
        {
            const int arow = tid >> 2;
            const int ak   = (tid & 3) << 2;
            float4 av = *reinterpret_cast<const float4*>(
                A + (size_t)(m0 + arow) * D_SZ + k0 + ak);
            As[ak + 0][arow] = av.x;
            As[ak + 1][arow] = av.y;
            As[ak + 2][arow] = av.z;
            As[ak + 3][arow] = av.w;
        }
        // Load W tile (16 k x 64 n)
        {
            const int brow = tid >> 4;
            const int bn   = (tid & 15) << 2;
            *reinterpret_cast<float4*>(&Bs[brow][bn]) =
                *reinterpret_cast<const float4*>(
                    W + (size_t)(k0 + brow) * D_SZ + n0 + bn);
        }
        __syncthreads();

#pragma unroll
        for (int k = 0; k < 16; k++) {
            float4 a  = *reinterpret_cast<const float4*>(&As[k][ty * 4]);
            float4 bv = *reinterpret_cast<const float4*>(&Bs[k][tx * 4]);
            acc[0][0] += a.x * bv.x; acc[0][1] += a.x * bv.y;
            acc[0][2] += a.x * bv.z; acc[0][3] += a.x * bv.w;
            acc[1][0] += a.y * bv.x; acc[1][1] += a.y * bv.y;
            acc[1][2] += a.y * bv.z; acc[1][3] += a.y * bv.w;
            acc[2][0] += a.z * bv.x; acc[2][1] += a.z * bv.y;
            acc[2][2] += a.z * bv.z; acc[2][3] += a.z * bv.w;
            acc[3][0] += a.w * bv.x; acc[3][1] += a.w * bv.y;
            acc[3][2] += a.w * bv.z; acc[3][3] += a.w * bv.w;
        }
        __syncthreads();
    }

    // Epilogue
    const float4 bb = *reinterpret_cast<const float4*>(bias + n0 + tx * 4);
#pragma unroll
    for (int i = 0; i < 4; i++) {
        const int m = m0 + ty * 4 + i;
        float4 res = make_float4(acc[i][0] + bb.x, acc[i][1] + bb.y,
                                 acc[i][2] + bb.z, acc[i][3] + bb.w);
        if (mode == 0) {
            *reinterpret_cast<float4*>(C + (size_t)m * D_SZ + n0 + tx * 4) = res;
        } else {
            const int b = m >> 11;           // m / 2048
            const int s = m & 2047;
            const int h = n0 >> 6;           // constant per block
            *reinterpret_cast<float4*>(
                C + (((size_t)(b * H_SZ + h) * S_SZ + s) * DK_SZ) + tx * 4) = res;
        }
    }
}

// ---------------------------------------------------------------------------
// Fused attention: one CTA per (b, h, q-row), 128 threads.
// scores -> mask -> softmax -> (optional) attn write -> context
// mask is int32 (JAX bool delivered as int32 by the harness).
// ---------------------------------------------------------------------------
__global__ void __launch_bounds__(128) attn_kernel(
    const int* __restrict__ mask,
    float* __restrict__ attn_out, int write_attn)
{
    __shared__ __align__(16) float kt[128 * 68];  // K tile [key][d]
    __shared__ __align__(16) float sc[S_SZ];      // score / prob row
    __shared__ float red[16];

    const int t  = threadIdx.x;
    const int qi = blockIdx.x;
    const int h  = blockIdx.y;
    const int b  = blockIdx.z;
    const int bh = b * H_SZ + h;

    // q row into registers
    const float* qrow = g_q + ((size_t)bh * S_SZ + qi) * DK_SZ;
    float4 qv[16];
#pragma unroll
    for (int i = 0; i < 16; i++)
        qv[i] = *reinterpret_cast<const float4*>(qrow + i * 4);

    const float* kb = g_k + (size_t)bh * S_SZ * DK_SZ;
    const int* mrow = mask + ((size_t)b * S_SZ + qi) * S_SZ;

    // ---- scores ----
    for (int j0 = 0; j0 < S_SZ; j0 += 128) {
        __syncthreads();
        const float4* src = reinterpret_cast<const float4*>(kb + (size_t)j0 * DK_SZ);
#pragma unroll
        for (int i = 0; i < 16; i++) {
            const int idx = t + i * 128;          // float4 index in 128x64 tile
            float4 v = src[idx];
            const int row = idx >> 4;             // key within tile
            const int col = (idx & 15) << 2;      // d
            *reinterpret_cast<float4*>(&kt[row * 68 + col]) = v;
        }
        __syncthreads();

        float acc = 0.f;
        const float4* krow4 = reinterpret_cast<const float4*>(&kt[t * 68]);
#pragma unroll
        for (int i = 0; i < 16; i++) {
            float4 kv = krow4[i];
            acc += qv[i].x * kv.x + qv[i].y * kv.y + qv[i].z * kv.z + qv[i].w * kv.w;
        }
        const int j = j0 + t;
        acc *= 0.125f;                            // 1/sqrt(64)
        if (mrow[j] != 0) acc = -1e9f;            // jnp.where(mask, NEG, scores)
        sc[j] = acc;
    }
    __syncthreads();

    // ---- softmax ----
    float mx = -1e30f;
    for (int j = t; j < S_SZ; j += 128) mx = fmaxf(mx, sc[j]);
#pragma unroll
    for (int o = 16; o; o >>= 1) mx = fmaxf(mx, __shfl_xor_sync(0xffffffffu, mx, o));
    if ((t & 31) == 0) red[t >> 5] = mx;
    __syncthreads();
    mx = fmaxf(fmaxf(red[0], red[1]), fmaxf(red[2], red[3]));

    float sum = 0.f;
    for (int j = t; j < S_SZ; j += 128) {
        float e = __expf(sc[j] - mx);
        sc[j] = e;
        sum += e;
    }
#pragma unroll
    for (int o = 16; o; o >>= 1) sum += __shfl_xor_sync(0xffffffffu, sum, o);
    if ((t & 31) == 0) red[4 + (t >> 5)] = sum;
    __syncthreads();
    const float inv = 1.f / (red[4] + red[5] + red[6] + red[7]);

    float* arow = attn_out + ((size_t)bh * S_SZ + qi) * S_SZ;
    if (write_attn) {
        for (int j = t; j < S_SZ; j += 128) {
            float p = sc[j] * inv;
            sc[j] = p;
            arow[j] = p;
        }
    } else {
        for (int j = t; j < S_SZ; j += 128) sc[j] *= inv;
    }
    __syncthreads();

    // ---- context: ctx[d] = sum_j p[j] * V[j][d] ----
    const int dg   = (t & 15) << 2;   // d group (float4)
    const int part = t >> 4;          // 8 j-partitions of 256
    const float* vb = g_v + (size_t)bh * S_SZ * DK_SZ;
    float cx = 0.f, cy = 0.f, cz = 0.f, cw = 0.f;
    const int jbeg = part * 256;
    for (int j = jbeg; j < jbeg + 256; j++) {
        const float p = sc[j];
        const float4 vv = *reinterpret_cast<const float4*>(vb + (size_t)j * DK_SZ + dg);
        cx += p * vv.x; cy += p * vv.y; cz += p * vv.z; cw += p * vv.w;
    }
    __syncthreads();
    float* cbuf = kt;                 // reuse smem: 8 parts x 64 d
    *reinterpret_cast<float4*>(&cbuf[part * 64 + dg]) = make_float4(cx, cy, cz, cw);
    __syncthreads();
    if (t < 64) {
        float s = 0.f;
#pragma unroll
        for (int p = 0; p < 8; p++) s += cbuf[p * 64 + t];
        g_ctx[((size_t)b * S_SZ + qi) * D_SZ + h * DK_SZ + t] = s;
    }
}

// ---------------------------------------------------------------------------
// Residual + LayerNorm: out = LN(g_o + Q) * gamma + beta  (one CTA per row)
// ---------------------------------------------------------------------------
__global__ void __launch_bounds__(256) ln_kernel(
    const float* __restrict__ resid, const float* __restrict__ gamma,
    const float* __restrict__ beta, float* __restrict__ out)
{
    __shared__ float rs[8], rq[8];
    const int row = blockIdx.x;
    const int t = threadIdx.x;

    const float4 a = reinterpret_cast<const float4*>(g_o + (size_t)row * D_SZ)[t];
    const float4 r = reinterpret_cast<const float4*>(resid + (size_t)row * D_SZ)[t];
    const float4 v = make_float4(a.x + r.x, a.y + r.y, a.z + r.z, a.w + r.w);

    float s  = v.x + v.y + v.z + v.w;
    float sq = v.x * v.x + v.y * v.y + v.z * v.z + v.w * v.w;
#pragma unroll
    for (int o = 16; o; o >>= 1) {
        s  += __shfl_xor_sync(0xffffffffu, s, o);
        sq += __shfl_xor_sync(0xffffffffu, sq, o);
    }
    if ((t & 31) == 0) { rs[t >> 5] = s; rq[t >> 5] = sq; }
    __syncthreads();
    float S = 0.f, SQ = 0.f;
#pragma unroll
    for (int i = 0; i < 8; i++) { S += rs[i]; SQ += rq[i]; }
    const float mu  = S * (1.f / D_SZ);
    const float var = SQ * (1.f / D_SZ) - mu * mu;
    const float rstd = rsqrtf(var + 1e-5f);

    const float4 g  = reinterpret_cast<const float4*>(gamma)[t];
    const float4 be = reinterpret_cast<const float4*>(beta)[t];
    reinterpret_cast<float4*>(out + (size_t)row * D_SZ)[t] =
        make_float4((v.x - mu) * rstd * g.x + be.x,
                    (v.y - mu) * rstd * g.y + be.y,
                    (v.z - mu) * rstd * g.z + be.z,
                    (v.w - mu) * rstd * g.w + be.w);
}

// ---------------------------------------------------------------------------
// kernel_launch
// Inputs (metadata order): Q K V attn_mask Wq bq Wk bk Wv bv Wo bo gamma beta
// Output: out [B,S,D] first; attn [B,H,S,S] appended if out_size allows.
// ---------------------------------------------------------------------------
extern "C" void kernel_launch(void* const* d_in, const int* in_sizes, int n_in,
                              void* d_out, int out_size)
{
    const float* Q  = (const float*)d_in[0];
    const float* K  = (const float*)d_in[1];
    const float* V  = (const float*)d_in[2];
    const int*   mask = (const int*)d_in[3];     // bool delivered as int32
    const float* Wq = (const float*)d_in[4];
    const float* bq = (const float*)d_in[5];
    const float* Wk = (const float*)d_in[6];
    const float* bk = (const float*)d_in[7];
    const float* Wv = (const float*)d_in[8];
    const float* bv = (const float*)d_in[9];
    const float* Wo = (const float*)d_in[10];
    const float* bo = (const float*)d_in[11];
    const float* gamma = (const float*)d_in[12];
    const float* beta  = (const float*)d_in[13];

    float *qp, *kp, *vp, *ctx, *op;
    cudaGetSymbolAddress((void**)&qp,  g_q);
    cudaGetSymbolAddress((void**)&kp,  g_k);
    cudaGetSymbolAddress((void**)&vp,  g_v);
    cudaGetSymbolAddress((void**)&ctx, g_ctx);
    cudaGetSymbolAddress((void**)&op,  g_o);

    float* outp = (float*)d_out;
    int write_attn = 0;
    float* attn_ptr = outp;  // dummy (unused when write_attn == 0)
    if ((long long)out_size >= (long long)OUT_ELEMS + (long long)ATTN_ELEMS) {
        write_attn = 1;
        attn_ptr = outp + OUT_ELEMS;
    }

    const dim3 gemm_grid(D_SZ / 64, M_SZ / 64);  // (16, 64)

    // QKV projections -> [b,h,s,64]
    gemm_kernel<<<gemm_grid, 256>>>(Q, Wq, bq, qp, 1);
    gemm_kernel<<<gemm_grid, 256>>>(K, Wk, bk, kp, 1);
    gemm_kernel<<<gemm_grid, 256>>>(V, Wv, bv, vp, 1);

    // attention
    attn_kernel<<<dim3(S_SZ, H_SZ, B_SZ), 128>>>(mask, attn_ptr, write_attn);

    // output projection
    gemm_kernel<<<gemm_grid, 256>>>(ctx, Wo, bo, op, 0);

    // residual + layernorm -> out
    ln_kernel<<<M_SZ, 256>>>(Q, gamma, beta, outp);
}

// round 4
// speedup vs baseline: 1.5965x; 1.5965x over previous
#include <cuda_runtime.h>

// ---------------------------------------------------------------------------
// Problem constants
// ---------------------------------------------------------------------------
#define B_SZ 2
#define S_SZ 2048
#define D_SZ 1024
#define H_SZ 16
#define DK_SZ 64
#define M_SZ (B_SZ * S_SZ)                    // 4096 rows
#define OUT_ELEMS (B_SZ * S_SZ * D_SZ)        // 4,194,304
#define ATTN_ELEMS (134217728)                // B*H*S*S

// Attention tiling
#define TQ 16                                 // q rows per CTA
#define SPAD 2052                             // score row stride (floats)
#define QS_OFF (TQ * SPAD)
#define VS_OFF (QS_OFF + TQ * 68)
#define SMEM_FLOATS (VS_OFF + 16 * 16 * 68)
#define SMEM_BYTES (SMEM_FLOATS * 4)          // 205312 B

// ---------------------------------------------------------------------------
// Scratch
// ---------------------------------------------------------------------------
__device__ float g_q[M_SZ * D_SZ];     // [b,h,s,dk]
__device__ float g_k[M_SZ * D_SZ];     // [b,h,s,dk]
__device__ float g_v[M_SZ * D_SZ];     // [b,h,s,dv]
__device__ float g_ctx[M_SZ * D_SZ];   // [b,s, h*dv]
__device__ float g_o[M_SZ * D_SZ];     // [b,s, d]

// ---------------------------------------------------------------------------
// Tiled fp32 GEMM v2: C = A[M,1024] @ W[1024,1024] + bias
// BM=128, BN=64, BK=16, 256 threads, 8x4 micro-tile.
//   mode 0: C row-major [M,1024]
//   mode 1: C written as [b, h, s, 64]
// ---------------------------------------------------------------------------
#define GBM 128
#define GBN 64
#define GBK 16

__global__ void __launch_bounds__(256) gemm_kernel(
    const float* __restrict__ A, const float* __restrict__ W,
    const float* __restrict__ bias, float* __restrict__ C, int mode)
{
    __shared__ __align__(16) float As[GBK][132];   // transposed A tile [k][m]
    __shared__ __align__(16) float Bs[GBK][68];    // B tile [k][n]

    const int tid = threadIdx.x;
    const int tx = tid & 15;        // n: 4-wide
    const int ty = tid >> 4;        // m: 8-wide
    const int m0 = blockIdx.y * GBM;
    const int n0 = blockIdx.x * GBN;

    float acc[8][4] = {};

    for (int k0 = 0; k0 < D_SZ; k0 += GBK) {
        // A tile: 128 rows x 16 k -> As[k][m]; 512 float4, 2 per thread
#pragma unroll
        for (int j = 0; j < 2; j++) {
            const int f = tid + j * 256;
            const int arow = f >> 2;
            const int ak   = (f & 3) << 2;
            float4 av = *reinterpret_cast<const float4*>(
                A + (size_t)(m0 + arow) * D_SZ + k0 + ak);
            As[ak + 0][arow] = av.x;
            As[ak + 1][arow] = av.y;
            As[ak + 2][arow] = av.z;
            As[ak + 3][arow] = av.w;
        }
        // B tile: 16 k x 64 n; 256 float4, 1 per thread
        {
            const int brow = tid >> 4;
            const int bn   = (tid & 15) << 2;
            *reinterpret_cast<float4*>(&Bs[brow][bn]) =
                *reinterpret_cast<const float4*>(
                    W + (size_t)(k0 + brow) * D_SZ + n0 + bn);
        }
        __syncthreads();

#pragma unroll
        for (int k = 0; k < GBK; k++) {
            const float4 a0 = *reinterpret_cast<const float4*>(&As[k][ty * 8]);
            const float4 a1 = *reinterpret_cast<const float4*>(&As[k][ty * 8 + 4]);
            const float4 bv = *reinterpret_cast<const float4*>(&Bs[k][tx * 4]);
            acc[0][0] += a0.x * bv.x; acc[0][1] += a0.x * bv.y;
            acc[0][2] += a0.x * bv.z; acc[0][3] += a0.x * bv.w;
            acc[1][0] += a0.y * bv.x; acc[1][1] += a0.y * bv.y;
            acc[1][2] += a0.y * bv.z; acc[1][3] += a0.y * bv.w;
            acc[2][0] += a0.z * bv.x; acc[2][1] += a0.z * bv.y;
            acc[2][2] += a0.z * bv.z; acc[2][3] += a0.z * bv.w;
            acc[3][0] += a0.w * bv.x; acc[3][1] += a0.w * bv.y;
            acc[3][2] += a0.w * bv.z; acc[3][3] += a0.w * bv.w;
            acc[4][0] += a1.x * bv.x; acc[4][1] += a1.x * bv.y;
            acc[4][2] += a1.x * bv.z; acc[4][3] += a1.x * bv.w;
            acc[5][0] += a1.y * bv.x; acc[5][1] += a1.y * bv.y;
            acc[5][2] += a1.y * bv.z; acc[5][3] += a1.y * bv.w;
            acc[6][0] += a1.z * bv.x; acc[6][1] += a1.z * bv.y;
            acc[6][2] += a1.z * bv.z; acc[6][3] += a1.z * bv.w;
            acc[7][0] += a1.w * bv.x; acc[7][1] += a1.w * bv.y;
            acc[7][2] += a1.w * bv.z; acc[7][3] += a1.w * bv.w;
        }
        __syncthreads();
    }

    const float4 bb = *reinterpret_cast<const float4*>(bias + n0 + tx * 4);
#pragma unroll
    for (int i = 0; i < 8; i++) {
        const int m = m0 + ty * 8 + i;
        float4 res = make_float4(acc[i][0] + bb.x, acc[i][1] + bb.y,
                                 acc[i][2] + bb.z, acc[i][3] + bb.w);
        if (mode == 0) {
            *reinterpret_cast<float4*>(C + (size_t)m * D_SZ + n0 + tx * 4) = res;
        } else {
            const int b = m >> 11;
            const int s = m & 2047;
            const int h = n0 >> 6;
            *reinterpret_cast<float4*>(
                C + (((size_t)(b * H_SZ + h) * S_SZ + s) * DK_SZ) + tx * 4) = res;
        }
    }
}

// ---------------------------------------------------------------------------
// Q-tiled fused attention (identical to round 2): one CTA per (b,h,16 q rows),
// 512 threads. Scores resident in smem; K in registers; V staged via smem.
// ---------------------------------------------------------------------------
__global__ void __launch_bounds__(512) attn_kernel(
    const int* __restrict__ mask,
    float* __restrict__ attn_out, int write_attn)
{
    extern __shared__ __align__(16) float sm[];
    float* sc = sm;                 // [16][SPAD] score / prob rows
    float* qs = sm + QS_OFF;        // [16][68]   q tile
    float* vs = sm + VS_OFF;        // [128][68] V tile / pbuf [16][16][68]

    const int t  = threadIdx.x;
    const int q0 = blockIdx.x * TQ;
    const int h  = blockIdx.y;
    const int b  = blockIdx.z;
    const int bh = b * H_SZ + h;

    // ---- load q tile ----
    {
        const float4* qg = reinterpret_cast<const float4*>(
            g_q + ((size_t)bh * S_SZ + q0) * DK_SZ);
        for (int i = t; i < TQ * 16; i += 512) {
            const int r = i >> 4, c = i & 15;
            reinterpret_cast<float4*>(qs)[r * 17 + c] = qg[i];
        }
    }
    __syncthreads();

    // ---- phase 1: scores ----
    const float* kb = g_k + (size_t)bh * S_SZ * DK_SZ;
    const int kh = t & 255;
    const int qh = t >> 8;
    const float4* qs4 = reinterpret_cast<const float4*>(qs);

    for (int tile = 0; tile < 8; tile++) {
        const float4* kr4 = reinterpret_cast<const float4*>(
            kb + (size_t)(tile * 256 + kh) * DK_SZ);
        float4 kr[16];
#pragma unroll
        for (int i = 0; i < 16; i++) kr[i] = kr4[i];

        float acc[8] = {};
#pragma unroll
        for (int i = 0; i < 16; i++) {
#pragma unroll
            for (int q = 0; q < 8; q++) {
                const float4 qv = qs4[(qh * 8 + q) * 17 + i];
                acc[q] += qv.x * kr[i].x + qv.y * kr[i].y
                        + qv.z * kr[i].z + qv.w * kr[i].w;
            }
        }
#pragma unroll
        for (int q = 0; q < 8; q++)
            sc[(qh * 8 + q) * SPAD + tile * 256 + kh] = acc[q] * 0.125f;
    }
    __syncthreads();

    // ---- phase 2: mask + softmax (+ attn write). One warp per q row. ----
    {
        const int w = t >> 5, lane = t & 31;
        const int* mrow = mask + ((size_t)b * S_SZ + (q0 + w)) * S_SZ;
        float* srow = sc + w * SPAD;

        float mx = -1e30f;
        for (int j = lane; j < S_SZ; j += 32) {
            float v = srow[j];
            if (mrow[j] != 0) v = -1e9f;
            srow[j] = v;
            mx = fmaxf(mx, v);
        }
#pragma unroll
        for (int o = 16; o; o >>= 1) mx = fmaxf(mx, __shfl_xor_sync(0xffffffffu, mx, o));

        float sum = 0.f;
        for (int j = lane; j < S_SZ; j += 32) {
            const float e = __expf(srow[j] - mx);
            srow[j] = e;
            sum += e;
        }
#pragma unroll
        for (int o = 16; o; o >>= 1) sum += __shfl_xor_sync(0xffffffffu, sum, o);
        const float inv = 1.f / sum;

        float4* srow4 = reinterpret_cast<float4*>(srow);
        if (write_attn) {
            float4* arow4 = reinterpret_cast<float4*>(
                attn_out + ((size_t)bh * S_SZ + (q0 + w)) * S_SZ);
            for (int i = lane; i < S_SZ / 4; i += 32) {
                float4 p = srow4[i];
                p.x *= inv; p.y *= inv; p.z *= inv; p.w *= inv;
                srow4[i] = p;
                arow4[i] = p;
            }
        } else {
            for (int i = lane; i < S_SZ / 4; i += 32) {
                float4 p = srow4[i];
                p.x *= inv; p.y *= inv; p.z *= inv; p.w *= inv;
                srow4[i] = p;
            }
        }
    }

    // ---- phase 3: context = P @ V ----
    const float* vb = g_v + (size_t)bh * S_SZ * DK_SZ;
    const int part = t >> 5;
    const int qgr  = (t >> 3) & 3;
    const int dg   = t & 7;
    float4* vs4 = reinterpret_cast<float4*>(vs);

    float4 c0[4], c1[4];
#pragma unroll
    for (int i = 0; i < 4; i++) {
        c0[i] = make_float4(0.f, 0.f, 0.f, 0.f);
        c1[i] = make_float4(0.f, 0.f, 0.f, 0.f);
    }

    for (int tile = 0; tile < 16; tile++) {
        __syncthreads();
        {
            const float4* src = reinterpret_cast<const float4*>(
                vb + (size_t)tile * 128 * DK_SZ);
            for (int i = t; i < 128 * 16; i += 512) {
                const int r = i >> 4, cc = i & 15;
                vs4[r * 17 + cc] = src[i];
            }
        }
        __syncthreads();

#pragma unroll
        for (int jj = 0; jj < 8; jj++) {
            const int jl = part * 8 + jj;
            const int j  = tile * 128 + jl;
            const float4 v0 = vs4[jl * 17 + dg * 2];
            const float4 v1 = vs4[jl * 17 + dg * 2 + 1];
#pragma unroll
            for (int i = 0; i < 4; i++) {
                const float p = sc[(qgr * 4 + i) * SPAD + j];
                c0[i].x += p * v0.x; c0[i].y += p * v0.y;
                c0[i].z += p * v0.z; c0[i].w += p * v0.w;
                c1[i].x += p * v1.x; c1[i].y += p * v1.y;
                c1[i].z += p * v1.z; c1[i].w += p * v1.w;
            }
        }
    }
    __syncthreads();

#pragma unroll
    for (int i = 0; i < 4; i++) {
        vs4[(part * 16 + qgr * 4 + i) * 17 + dg * 2]     = c0[i];
        vs4[(part * 16 + qgr * 4 + i) * 17 + dg * 2 + 1] = c1[i];
    }
    __syncthreads();

    if (t < 256) {
        const int q  = t >> 4;
        const int dq = t & 15;
        float4 s = make_float4(0.f, 0.f, 0.f, 0.f);
#pragma unroll
        for (int p = 0; p < 16; p++) {
            const float4 x = vs4[(p * 16 + q) * 17 + dq];
            s.x += x.x; s.y += x.y; s.z += x.z; s.w += x.w;
        }
        *reinterpret_cast<float4*>(
            g_ctx + ((size_t)(b * S_SZ + q0 + q)) * D_SZ + h * DK_SZ + dq * 4) = s;
    }
}

// ---------------------------------------------------------------------------
// Residual + LayerNorm
// ---------------------------------------------------------------------------
__global__ void __launch_bounds__(256) ln_kernel(
    const float* __restrict__ resid, const float* __restrict__ gamma,
    const float* __restrict__ beta, float* __restrict__ out)
{
    __shared__ float rs[8], rq[8];
    const int row = blockIdx.x;
    const int t = threadIdx.x;

    const float4 a = reinterpret_cast<const float4*>(g_o + (size_t)row * D_SZ)[t];
    const float4 r = reinterpret_cast<const float4*>(resid + (size_t)row * D_SZ)[t];
    const float4 v = make_float4(a.x + r.x, a.y + r.y, a.z + r.z, a.w + r.w);

    float s  = v.x + v.y + v.z + v.w;
    float sq = v.x * v.x + v.y * v.y + v.z * v.z + v.w * v.w;
#pragma unroll
    for (int o = 16; o; o >>= 1) {
        s  += __shfl_xor_sync(0xffffffffu, s, o);
        sq += __shfl_xor_sync(0xffffffffu, sq, o);
    }
    if ((t & 31) == 0) { rs[t >> 5] = s; rq[t >> 5] = sq; }
    __syncthreads();
    float S = 0.f, SQ = 0.f;
#pragma unroll
    for (int i = 0; i < 8; i++) { S += rs[i]; SQ += rq[i]; }
    const float mu  = S * (1.f / D_SZ);
    const float var = SQ * (1.f / D_SZ) - mu * mu;
    const float rstd = rsqrtf(var + 1e-5f);

    const float4 g  = reinterpret_cast<const float4*>(gamma)[t];
    const float4 be = reinterpret_cast<const float4*>(beta)[t];
    reinterpret_cast<float4*>(out + (size_t)row * D_SZ)[t] =
        make_float4((v.x - mu) * rstd * g.x + be.x,
                    (v.y - mu) * rstd * g.y + be.y,
                    (v.z - mu) * rstd * g.z + be.z,
                    (v.w - mu) * rstd * g.w + be.w);
}

// ---------------------------------------------------------------------------
// kernel_launch
// ---------------------------------------------------------------------------
extern "C" void kernel_launch(void* const* d_in, const int* in_sizes, int n_in,
                              void* d_out, int out_size)
{
    const float* Q  = (const float*)d_in[0];
    const float* K  = (const float*)d_in[1];
    const float* V  = (const float*)d_in[2];
    const int*   mask = (const int*)d_in[3];
    const float* Wq = (const float*)d_in[4];
    const float* bq = (const float*)d_in[5];
    const float* Wk = (const float*)d_in[6];
    const float* bk = (const float*)d_in[7];
    const float* Wv = (const float*)d_in[8];
    const float* bv = (const float*)d_in[9];
    const float* Wo = (const float*)d_in[10];
    const float* bo = (const float*)d_in[11];
    const float* gamma = (const float*)d_in[12];
    const float* beta  = (const float*)d_in[13];

    float *qp, *kp, *vp, *ctx, *op;
    cudaGetSymbolAddress((void**)&qp,  g_q);
    cudaGetSymbolAddress((void**)&kp,  g_k);
    cudaGetSymbolAddress((void**)&vp,  g_v);
    cudaGetSymbolAddress((void**)&ctx, g_ctx);
    cudaGetSymbolAddress((void**)&op,  g_o);

    float* outp = (float*)d_out;
    int write_attn = 0;
    float* attn_ptr = outp;
    if ((long long)out_size >= (long long)OUT_ELEMS + (long long)ATTN_ELEMS) {
        write_attn = 1;
        attn_ptr = outp + OUT_ELEMS;
    }

    cudaFuncSetAttribute(attn_kernel,
        cudaFuncAttributeMaxDynamicSharedMemorySize, SMEM_BYTES);

    const dim3 gemm_grid(D_SZ / GBN, M_SZ / GBM);   // (16, 32)

    gemm_kernel<<<gemm_grid, 256>>>(Q, Wq, bq, qp, 1);
    gemm_kernel<<<gemm_grid, 256>>>(K, Wk, bk, kp, 1);
    gemm_kernel<<<gemm_grid, 256>>>(V, Wv, bv, vp, 1);

    attn_kernel<<<dim3(S_SZ / TQ, H_SZ, B_SZ), 512, SMEM_BYTES>>>(
        mask, attn_ptr, write_attn);

    gemm_kernel<<<gemm_grid, 256>>>(ctx, Wo, bo, op, 0);

    ln_kernel<<<M_SZ, 256>>>(Q, gamma, beta, outp);
}

// round 7
// speedup vs baseline: 3.3532x; 2.1003x over previous
#include <cuda_runtime.h>
#include <cuda_bf16.h>
#include <cstdint>

// ---------------------------------------------------------------------------
// Problem constants
// ---------------------------------------------------------------------------
#define B_SZ 2
#define S_SZ 2048
#define D_SZ 1024
#define H_SZ 16
#define DK_SZ 64
#define BH_SZ (B_SZ * H_SZ)                   // 32
#define M_SZ (B_SZ * S_SZ)                    // 4096
#define OUT_ELEMS (B_SZ * S_SZ * D_SZ)        // 4,194,304
#define ATTN_ELEMS (134217728)                // B*H*S*S

// ---------------------------------------------------------------------------
// Scratch
// ---------------------------------------------------------------------------
__device__ float g_q[M_SZ * D_SZ];            // [bh,s,dk] fp32
__device__ float g_k[M_SZ * D_SZ];
__device__ float g_v[M_SZ * D_SZ];
__device__ float g_ctx[M_SZ * D_SZ];          // [b,s,h*dv]
__device__ float g_o[M_SZ * D_SZ];
__device__ __nv_bfloat16 g_q1[M_SZ * D_SZ];   // bf16 hi/lo splits
__device__ __nv_bfloat16 g_q2[M_SZ * D_SZ];
__device__ __nv_bfloat16 g_k1[M_SZ * D_SZ];
__device__ __nv_bfloat16 g_k2[M_SZ * D_SZ];
__device__ __nv_bfloat16 g_vt1[M_SZ * D_SZ];  // V transposed: [bh][d][s]
__device__ __nv_bfloat16 g_vt2[M_SZ * D_SZ];
__device__ float g_sc[ATTN_ELEMS];            // score/prob scratch (if !write_attn)

// ---------------------------------------------------------------------------
// Warp MMA helpers (sm_80+ features only; no 'a'-suffix instructions)
// ---------------------------------------------------------------------------
__device__ __forceinline__ uint32_t smem_u32(const void* p) {
    uint32_t a;
    asm("{ .reg .u64 t; cvta.to.shared.u64 t, %1; cvt.u32.u64 %0, t; }"
        : "=r"(a) : "l"(p));
    return a;
}

__device__ __forceinline__ void mma_bf16(float* c, const uint32_t* a,
                                         const uint32_t* b) {
    asm volatile(
        "mma.sync.aligned.m16n8k16.row.col.f32.bf16.bf16.f32 "
        "{%0,%1,%2,%3}, {%4,%5,%6,%7}, {%8,%9}, {%0,%1,%2,%3};"
        : "+f"(c[0]), "+f"(c[1]), "+f"(c[2]), "+f"(c[3])
        : "r"(a[0]), "r"(a[1]), "r"(a[2]), "r"(a[3]),
          "r"(b[0]), "r"(b[1]));
}

__device__ __forceinline__ void ldsm_x4(uint32_t* r, uint32_t addr) {
    asm volatile("ldmatrix.sync.aligned.m8n8.x4.shared.b16 {%0,%1,%2,%3}, [%4];"
                 : "=r"(r[0]), "=r"(r[1]), "=r"(r[2]), "=r"(r[3]) : "r"(addr));
}
__device__ __forceinline__ void ldsm_x2(uint32_t* r, uint32_t addr) {
    asm volatile("ldmatrix.sync.aligned.m8n8.x2.shared.b16 {%0,%1}, [%2];"
                 : "=r"(r[0]), "=r"(r[1]) : "r"(addr));
}

__device__ __forceinline__ uint32_t bf2pack(__nv_bfloat16 a, __nv_bfloat16 b) {
    __nv_bfloat162 v = {a, b};
    return *reinterpret_cast<uint32_t*>(&v);
}

// Tile stride: 72 bf16 per row (144 B -> conflict-staggered, 16B aligned)
#define TSTR 72

// ---------------------------------------------------------------------------
// fp32 GEMM (verified): C = A[M,1024] @ W[1024,1024] + bias
// ---------------------------------------------------------------------------
#define GBM 128
#define GBN 64
#define GBK 16

__global__ void __launch_bounds__(256) gemm_kernel(
    const float* __restrict__ A, const float* __restrict__ W,
    const float* __restrict__ bias, float* __restrict__ C, int mode)
{
    __shared__ __align__(16) float As[GBK][132];
    __shared__ __align__(16) float Bs[GBK][68];

    const int tid = threadIdx.x;
    const int tx = tid & 15;
    const int ty = tid >> 4;
    const int m0 = blockIdx.y * GBM;
    const int n0 = blockIdx.x * GBN;

    float acc[8][4] = {};

    for (int k0 = 0; k0 < D_SZ; k0 += GBK) {
#pragma unroll
        for (int j = 0; j < 2; j++) {
            const int f = tid + j * 256;
            const int arow = f >> 2;
            const int ak   = (f & 3) << 2;
            float4 av = *reinterpret_cast<const float4*>(
                A + (size_t)(m0 + arow) * D_SZ + k0 + ak);
            As[ak + 0][arow] = av.x;
            As[ak + 1][arow] = av.y;
            As[ak + 2][arow] = av.z;
            As[ak + 3][arow] = av.w;
        }
        {
            const int brow = tid >> 4;
            const int bn   = (tid & 15) << 2;
            *reinterpret_cast<float4*>(&Bs[brow][bn]) =
                *reinterpret_cast<const float4*>(
                    W + (size_t)(k0 + brow) * D_SZ + n0 + bn);
        }
        __syncthreads();

#pragma unroll
        for (int k = 0; k < GBK; k++) {
            const float4 a0 = *reinterpret_cast<const float4*>(&As[k][ty * 8]);
            const float4 a1 = *reinterpret_cast<const float4*>(&As[k][ty * 8 + 4]);
            const float4 bv = *reinterpret_cast<const float4*>(&Bs[k][tx * 4]);
            acc[0][0] += a0.x * bv.x; acc[0][1] += a0.x * bv.y;
            acc[0][2] += a0.x * bv.z; acc[0][3] += a0.x * bv.w;
            acc[1][0] += a0.y * bv.x; acc[1][1] += a0.y * bv.y;
            acc[1][2] += a0.y * bv.z; acc[1][3] += a0.y * bv.w;
            acc[2][0] += a0.z * bv.x; acc[2][1] += a0.z * bv.y;
            acc[2][2] += a0.z * bv.z; acc[2][3] += a0.z * bv.w;
            acc[3][0] += a0.w * bv.x; acc[3][1] += a0.w * bv.y;
            acc[3][2] += a0.w * bv.z; acc[3][3] += a0.w * bv.w;
            acc[4][0] += a1.x * bv.x; acc[4][1] += a1.x * bv.y;
            acc[4][2] += a1.x * bv.z; acc[4][3] += a1.x * bv.w;
            acc[5][0] += a1.y * bv.x; acc[5][1] += a1.y * bv.y;
            acc[5][2] += a1.y * bv.z; acc[5][3] += a1.y * bv.w;
            acc[6][0] += a1.z * bv.x; acc[6][1] += a1.z * bv.y;
            acc[6][2] += a1.z * bv.z; acc[6][3] += a1.z * bv.w;
            acc[7][0] += a1.w * bv.x; acc[7][1] += a1.w * bv.y;
            acc[7][2] += a1.w * bv.z; acc[7][3] += a1.w * bv.w;
        }
        __syncthreads();
    }

    const float4 bb = *reinterpret_cast<const float4*>(bias + n0 + tx * 4);
#pragma unroll
    for (int i = 0; i < 8; i++) {
        const int m = m0 + ty * 8 + i;
        float4 res = make_float4(acc[i][0] + bb.x, acc[i][1] + bb.y,
                                 acc[i][2] + bb.z, acc[i][3] + bb.w);
        if (mode == 0) {
            *reinterpret_cast<float4*>(C + (size_t)m * D_SZ + n0 + tx * 4) = res;
        } else {
            const int b = m >> 11;
            const int s = m & 2047;
            const int h = n0 >> 6;
            *reinterpret_cast<float4*>(
                C + (((size_t)(b * H_SZ + h) * S_SZ + s) * DK_SZ) + tx * 4) = res;
        }
    }
}

// ---------------------------------------------------------------------------
// fp32 -> bf16 hi/lo split (elementwise)
// ---------------------------------------------------------------------------
__global__ void __launch_bounds__(256) split_kernel(
    const float* __restrict__ in, __nv_bfloat16* __restrict__ hi,
    __nv_bfloat16* __restrict__ lo)
{
    const int i = blockIdx.x * 256 + threadIdx.x;
    const float4 v = reinterpret_cast<const float4*>(in)[i];
    __nv_bfloat16 h0 = __float2bfloat16(v.x);
    __nv_bfloat16 h1 = __float2bfloat16(v.y);
    __nv_bfloat16 h2 = __float2bfloat16(v.z);
    __nv_bfloat16 h3 = __float2bfloat16(v.w);
    __nv_bfloat162 H0 = {h0, h1}, H1 = {h2, h3};
    __nv_bfloat162 L0 = {__float2bfloat16(v.x - __bfloat162float(h0)),
                         __float2bfloat16(v.y - __bfloat162float(h1))};
    __nv_bfloat162 L1 = {__float2bfloat16(v.z - __bfloat162float(h2)),
                         __float2bfloat16(v.w - __bfloat162float(h3))};
    reinterpret_cast<__nv_bfloat162*>(hi)[i * 2]     = H0;
    reinterpret_cast<__nv_bfloat162*>(hi)[i * 2 + 1] = H1;
    reinterpret_cast<__nv_bfloat162*>(lo)[i * 2]     = L0;
    reinterpret_cast<__nv_bfloat162*>(lo)[i * 2 + 1] = L1;
}

// ---------------------------------------------------------------------------
// V transpose + split: g_v [bh][s][64] -> g_vt1/2 [bh][64][2048]
// ---------------------------------------------------------------------------
__global__ void __launch_bounds__(128) vt_kernel()
{
    __shared__ float vs[128][65];
    const int jt = blockIdx.x;            // 0..15
    const int bh = blockIdx.y;            // 0..31
    const int t  = threadIdx.x;
    const int j0 = jt * 128;

    const float4* src = reinterpret_cast<const float4*>(
        g_v + ((size_t)bh * S_SZ + j0) * DK_SZ);
    for (int i = t; i < 128 * 16; i += 128) {
        const int r = i >> 4, c = i & 15;
        const float4 v = src[i];
        vs[r][c * 4 + 0] = v.x; vs[r][c * 4 + 1] = v.y;
        vs[r][c * 4 + 2] = v.z; vs[r][c * 4 + 3] = v.w;
    }
    __syncthreads();

    for (int i = t; i < 64 * 128; i += 128) {
        const int j = i & 127;
        const int d = i >> 7;
        const float x = vs[j][d];
        const __nv_bfloat16 h = __float2bfloat16(x);
        const __nv_bfloat16 l = __float2bfloat16(x - __bfloat162float(h));
        const size_t o = ((size_t)bh * 64 + d) * S_SZ + j0 + j;
        g_vt1[o] = h;
        g_vt2[o] = l;
    }
}

// ---------------------------------------------------------------------------
// Score kernel (warp MMA, bf16x3): CTA = 128q x 128k, 8 warps (32q x 64k each)
// ---------------------------------------------------------------------------
#define SQ_H 0
#define SQ_L (128 * TSTR)
#define SK_H (2 * 128 * TSTR)
#define SK_L (3 * 128 * TSTR)
#define SCORE_SMEM (4 * 128 * TSTR * 2)       // 73728 B

__global__ void __launch_bounds__(256) score_kernel(
    const int* __restrict__ mask, float* __restrict__ sbuf)
{
    extern __shared__ __align__(16) __nv_bfloat16 sm[];
    const int t = threadIdx.x;
    const int lane = t & 31, wid = t >> 5;
    const int wq = wid & 3, wk = wid >> 2;    // 4 q-warps x 2 k-warps
    const int q0 = blockIdx.x * 128, k0 = blockIdx.y * 128;
    const int bh = blockIdx.z, b = bh >> 4;

    // stage Q/K hi+lo tiles (both 128x64, contiguous in gmem)
    {
        const uint4* q1 = reinterpret_cast<const uint4*>(
            g_q1 + ((size_t)bh * S_SZ + q0) * DK_SZ);
        const uint4* q2 = reinterpret_cast<const uint4*>(
            g_q2 + ((size_t)bh * S_SZ + q0) * DK_SZ);
        const uint4* k1 = reinterpret_cast<const uint4*>(
            g_k1 + ((size_t)bh * S_SZ + k0) * DK_SZ);
        const uint4* k2 = reinterpret_cast<const uint4*>(
            g_k2 + ((size_t)bh * S_SZ + k0) * DK_SZ);
        for (int i = t; i < 1024; i += 256) {
            const int r = i >> 3, c = i & 7;
            const int off = r * TSTR + c * 8;
            *reinterpret_cast<uint4*>(
                reinterpret_cast<char*>(sm) + (size_t)(SQ_H + off) * 2) = q1[i];
            *reinterpret_cast<uint4*>(
                reinterpret_cast<char*>(sm) + (size_t)(SQ_L + off) * 2) = q2[i];
            *reinterpret_cast<uint4*>(
                reinterpret_cast<char*>(sm) + (size_t)(SK_H + off) * 2) = k1[i];
            *reinterpret_cast<uint4*>(
                reinterpret_cast<char*>(sm) + (size_t)(SK_L + off) * 2) = k2[i];
        }
    }
    __syncthreads();

    const uint32_t sb = smem_u32(sm);
    float acc[2][8][4] = {};

#pragma unroll
    for (int ks = 0; ks < 4; ks++) {
        const int kc = ks * 16;
        uint32_t ah[2][4], al[2][4];
#pragma unroll
        for (int mi = 0; mi < 2; mi++) {
            const int row = wq * 32 + mi * 16 + (lane & 15);
            const int col = kc + ((lane >> 4) << 3);
            ldsm_x4(ah[mi], sb + (uint32_t)(SQ_H + row * TSTR + col) * 2);
            ldsm_x4(al[mi], sb + (uint32_t)(SQ_L + row * TSTR + col) * 2);
        }
#pragma unroll
        for (int ni = 0; ni < 8; ni++) {
            uint32_t bh_[2], bl_[2];
            const int row = wk * 64 + ni * 8 + (lane & 7);
            const int col = kc + (((lane >> 3) & 1) << 3);
            ldsm_x2(bh_, sb + (uint32_t)(SK_H + row * TSTR + col) * 2);
            ldsm_x2(bl_, sb + (uint32_t)(SK_L + row * TSTR + col) * 2);
#pragma unroll
            for (int mi = 0; mi < 2; mi++) {
                mma_bf16(acc[mi][ni], ah[mi], bh_);
                mma_bf16(acc[mi][ni], ah[mi], bl_);
                mma_bf16(acc[mi][ni], al[mi], bh_);
            }
        }
    }

    // epilogue: scale, mask, store
    const int g  = lane >> 2;
    const int tg = lane & 3;
#pragma unroll
    for (int mi = 0; mi < 2; mi++) {
#pragma unroll
        for (int ni = 0; ni < 8; ni++) {
            const int q = q0 + wq * 32 + mi * 16 + g;
            const int k = k0 + wk * 64 + ni * 8 + tg * 2;
            const int2 m0 = *reinterpret_cast<const int2*>(
                mask + ((size_t)b * S_SZ + q) * S_SZ + k);
            const int2 m1 = *reinterpret_cast<const int2*>(
                mask + ((size_t)b * S_SZ + q + 8) * S_SZ + k);
            float2 s0, s1;
            s0.x = m0.x ? -1e9f : acc[mi][ni][0] * 0.125f;
            s0.y = m0.y ? -1e9f : acc[mi][ni][1] * 0.125f;
            s1.x = m1.x ? -1e9f : acc[mi][ni][2] * 0.125f;
            s1.y = m1.y ? -1e9f : acc[mi][ni][3] * 0.125f;
            *reinterpret_cast<float2*>(
                sbuf + ((size_t)bh * S_SZ + q) * S_SZ + k) = s0;
            *reinterpret_cast<float2*>(
                sbuf + ((size_t)bh * S_SZ + q + 8) * S_SZ + k) = s1;
        }
    }
}

// ---------------------------------------------------------------------------
// Softmax (in place over rows of 2048)
// ---------------------------------------------------------------------------
__global__ void __launch_bounds__(256) softmax_kernel(float* __restrict__ buf)
{
    __shared__ float red[8];
    const size_t row = blockIdx.x;
    const int t = threadIdx.x;
    float4* p4 = reinterpret_cast<float4*>(buf + row * S_SZ);

    float4 v0 = p4[t], v1 = p4[t + 256];
    float mx = fmaxf(fmaxf(fmaxf(v0.x, v0.y), fmaxf(v0.z, v0.w)),
                     fmaxf(fmaxf(v1.x, v1.y), fmaxf(v1.z, v1.w)));
#pragma unroll
    for (int o = 16; o; o >>= 1) mx = fmaxf(mx, __shfl_xor_sync(0xffffffffu, mx, o));
    if ((t & 31) == 0) red[t >> 5] = mx;
    __syncthreads();
    mx = fmaxf(fmaxf(fmaxf(red[0], red[1]), fmaxf(red[2], red[3])),
               fmaxf(fmaxf(red[4], red[5]), fmaxf(red[6], red[7])));
    __syncthreads();

    v0.x = __expf(v0.x - mx); v0.y = __expf(v0.y - mx);
    v0.z = __expf(v0.z - mx); v0.w = __expf(v0.w - mx);
    v1.x = __expf(v1.x - mx); v1.y = __expf(v1.y - mx);
    v1.z = __expf(v1.z - mx); v1.w = __expf(v1.w - mx);
    float sum = v0.x + v0.y + v0.z + v0.w + v1.x + v1.y + v1.z + v1.w;
#pragma unroll
    for (int o = 16; o; o >>= 1) sum += __shfl_xor_sync(0xffffffffu, sum, o);
    if ((t & 31) == 0) red[t >> 5] = sum;
    __syncthreads();
    const float inv = 1.f / (red[0] + red[1] + red[2] + red[3] +
                             red[4] + red[5] + red[6] + red[7]);

    v0.x *= inv; v0.y *= inv; v0.z *= inv; v0.w *= inv;
    v1.x *= inv; v1.y *= inv; v1.z *= inv; v1.w *= inv;
    p4[t] = v0;
    p4[t + 256] = v1;
}

// ---------------------------------------------------------------------------
// Context kernel (warp MMA, bf16x3): CTA = 128q x 64d, K=2048 in 32 chunks.
// ---------------------------------------------------------------------------
#define CP_H 0
#define CP_L (128 * TSTR)
#define CV_H (2 * 128 * TSTR)
#define CV_L (2 * 128 * TSTR + 64 * TSTR)
#define CTX_SMEM ((2 * 128 * TSTR + 2 * 64 * TSTR) * 2)   // 55296 B

__global__ void __launch_bounds__(256) ctx_kernel(const float* __restrict__ probs)
{
    extern __shared__ __align__(16) __nv_bfloat16 sm[];
    const int t = threadIdx.x;
    const int lane = t & 31, wid = t >> 5;    // 8 warps, 16 q rows each
    const int q0 = blockIdx.x * 128;
    const int bh = blockIdx.y, b = bh >> 4, h = bh & 15;
    const uint32_t sb = smem_u32(sm);

    const float* prow = probs + ((size_t)bh * S_SZ + q0) * S_SZ;
    const __nv_bfloat16* vt1 = g_vt1 + (size_t)bh * 64 * S_SZ;
    const __nv_bfloat16* vt2 = g_vt2 + (size_t)bh * 64 * S_SZ;

    float acc[8][4] = {};

    for (int ch = 0; ch < 32; ch++) {
        const int j0 = ch * 64;
        __syncthreads();
        // stage P (fp32 -> hi/lo bf16): 128 rows x 16 float4
        for (int i = t; i < 2048; i += 256) {
            const int r = i >> 4, c = i & 15;
            const float4 v = *reinterpret_cast<const float4*>(
                prow + (size_t)r * S_SZ + j0 + c * 4);
            const __nv_bfloat16 h0 = __float2bfloat16(v.x);
            const __nv_bfloat16 h1 = __float2bfloat16(v.y);
            const __nv_bfloat16 h2 = __float2bfloat16(v.z);
            const __nv_bfloat16 h3 = __float2bfloat16(v.w);
            const uint2 hp = make_uint2(bf2pack(h0, h1), bf2pack(h2, h3));
            const uint2 lp = make_uint2(
                bf2pack(__float2bfloat16(v.x - __bfloat162float(h0)),
                        __float2bfloat16(v.y - __bfloat162float(h1))),
                bf2pack(__float2bfloat16(v.z - __bfloat162float(h2)),
                        __float2bfloat16(v.w - __bfloat162float(h3))));
            const int off = r * TSTR + c * 4;
            *reinterpret_cast<uint2*>(
                reinterpret_cast<char*>(sm) + (size_t)(CP_H + off) * 2) = hp;
            *reinterpret_cast<uint2*>(
                reinterpret_cast<char*>(sm) + (size_t)(CP_L + off) * 2) = lp;
        }
        // stage V^T hi/lo: 64 rows x 8 uint4
        for (int i = t; i < 512; i += 256) {
            const int r = i >> 3, c = i & 7;
            const int off = r * TSTR + c * 8;
            *reinterpret_cast<uint4*>(
                reinterpret_cast<char*>(sm) + (size_t)(CV_H + off) * 2) =
                *reinterpret_cast<const uint4*>(vt1 + (size_t)r * S_SZ + j0 + c * 8);
            *reinterpret_cast<uint4*>(
                reinterpret_cast<char*>(sm) + (size_t)(CV_L + off) * 2) =
                *reinterpret_cast<const uint4*>(vt2 + (size_t)r * S_SZ + j0 + c * 8);
        }
        __syncthreads();

#pragma unroll
        for (int ks = 0; ks < 4; ks++) {
            const int kc = ks * 16;
            uint32_t ah[4], al[4];
            {
                const int row = wid * 16 + (lane & 15);
                const int col = kc + ((lane >> 4) << 3);
                ldsm_x4(ah, sb + (uint32_t)(CP_H + row * TSTR + col) * 2);
                ldsm_x4(al, sb + (uint32_t)(CP_L + row * TSTR + col) * 2);
            }
#pragma unroll
            for (int ni = 0; ni < 8; ni++) {
                uint32_t bh_[2], bl_[2];
                const int row = ni * 8 + (lane & 7);
                const int col = kc + (((lane >> 3) & 1) << 3);
                ldsm_x2(bh_, sb + (uint32_t)(CV_H + row * TSTR + col) * 2);
                ldsm_x2(bl_, sb + (uint32_t)(CV_L + row * TSTR + col) * 2);
                mma_bf16(acc[ni], ah, bh_);
                mma_bf16(acc[ni], ah, bl_);
                mma_bf16(acc[ni], al, bh_);
            }
        }
    }

    // epilogue
    const int g  = lane >> 2;
    const int tg = lane & 3;
#pragma unroll
    for (int ni = 0; ni < 8; ni++) {
        const int q = q0 + wid * 16 + g;
        const int d = ni * 8 + tg * 2;
        *reinterpret_cast<float2*>(
            g_ctx + ((size_t)(b * S_SZ + q)) * D_SZ + h * DK_SZ + d) =
            make_float2(acc[ni][0], acc[ni][1]);
        *reinterpret_cast<float2*>(
            g_ctx + ((size_t)(b * S_SZ + q + 8)) * D_SZ + h * DK_SZ + d) =
            make_float2(acc[ni][2], acc[ni][3]);
    }
}

// ---------------------------------------------------------------------------
// Residual + LayerNorm
// ---------------------------------------------------------------------------
__global__ void __launch_bounds__(256) ln_kernel(
    const float* __restrict__ resid, const float* __restrict__ gamma,
    const float* __restrict__ beta, float* __restrict__ out)
{
    __shared__ float rs[8], rq[8];
    const int row = blockIdx.x;
    const int t = threadIdx.x;

    const float4 a = reinterpret_cast<const float4*>(g_o + (size_t)row * D_SZ)[t];
    const float4 r = reinterpret_cast<const float4*>(resid + (size_t)row * D_SZ)[t];
    const float4 v = make_float4(a.x + r.x, a.y + r.y, a.z + r.z, a.w + r.w);

    float s  = v.x + v.y + v.z + v.w;
    float sq = v.x * v.x + v.y * v.y + v.z * v.z + v.w * v.w;
#pragma unroll
    for (int o = 16; o; o >>= 1) {
        s  += __shfl_xor_sync(0xffffffffu, s, o);
        sq += __shfl_xor_sync(0xffffffffu, sq, o);
    }
    if ((t & 31) == 0) { rs[t >> 5] = s; rq[t >> 5] = sq; }
    __syncthreads();
    float S = 0.f, SQ = 0.f;
#pragma unroll
    for (int i = 0; i < 8; i++) { S += rs[i]; SQ += rq[i]; }
    const float mu  = S * (1.f / D_SZ);
    const float var = SQ * (1.f / D_SZ) - mu * mu;
    const float rstd = rsqrtf(var + 1e-5f);

    const float4 g  = reinterpret_cast<const float4*>(gamma)[t];
    const float4 be = reinterpret_cast<const float4*>(beta)[t];
    reinterpret_cast<float4*>(out + (size_t)row * D_SZ)[t] =
        make_float4((v.x - mu) * rstd * g.x + be.x,
                    (v.y - mu) * rstd * g.y + be.y,
                    (v.z - mu) * rstd * g.z + be.z,
                    (v.w - mu) * rstd * g.w + be.w);
}

// ---------------------------------------------------------------------------
// kernel_launch
// ---------------------------------------------------------------------------
extern "C" void kernel_launch(void* const* d_in, const int* in_sizes, int n_in,
                              void* d_out, int out_size)
{
    const float* Q  = (const float*)d_in[0];
    const float* K  = (const float*)d_in[1];
    const float* V  = (const float*)d_in[2];
    const int*   mask = (const int*)d_in[3];
    const float* Wq = (const float*)d_in[4];
    const float* bq = (const float*)d_in[5];
    const float* Wk = (const float*)d_in[6];
    const float* bk = (const float*)d_in[7];
    const float* Wv = (const float*)d_in[8];
    const float* bv = (const float*)d_in[9];
    const float* Wo = (const float*)d_in[10];
    const float* bo = (const float*)d_in[11];
    const float* gamma = (const float*)d_in[12];
    const float* beta  = (const float*)d_in[13];

    float *qp, *kp, *vp, *ctx, *op, *scp;
    __nv_bfloat16 *q1, *q2, *k1, *k2;
    cudaGetSymbolAddress((void**)&qp,  g_q);
    cudaGetSymbolAddress((void**)&kp,  g_k);
    cudaGetSymbolAddress((void**)&vp,  g_v);
    cudaGetSymbolAddress((void**)&ctx, g_ctx);
    cudaGetSymbolAddress((void**)&op,  g_o);
    cudaGetSymbolAddress((void**)&scp, g_sc);
    cudaGetSymbolAddress((void**)&q1,  g_q1);
    cudaGetSymbolAddress((void**)&q2,  g_q2);
    cudaGetSymbolAddress((void**)&k1,  g_k1);
    cudaGetSymbolAddress((void**)&k2,  g_k2);

    float* outp = (float*)d_out;
    float* sbuf = scp;
    if ((long long)out_size >= (long long)OUT_ELEMS + (long long)ATTN_ELEMS)
        sbuf = outp + OUT_ELEMS;   // probs land directly in the attn output

    cudaFuncSetAttribute(score_kernel,
        cudaFuncAttributeMaxDynamicSharedMemorySize, SCORE_SMEM);
    cudaFuncSetAttribute(ctx_kernel,
        cudaFuncAttributeMaxDynamicSharedMemorySize, CTX_SMEM);

    const dim3 gemm_grid(D_SZ / GBN, M_SZ / GBM);

    // QKV projections (fp32) -> [bh,s,64]
    gemm_kernel<<<gemm_grid, 256>>>(Q, Wq, bq, qp, 1);
    gemm_kernel<<<gemm_grid, 256>>>(K, Wk, bk, kp, 1);
    gemm_kernel<<<gemm_grid, 256>>>(V, Wv, bv, vp, 1);

    // bf16 splits of q, k; V transpose+split
    split_kernel<<<(M_SZ * D_SZ / 4) / 256, 256>>>(qp, q1, q2);
    split_kernel<<<(M_SZ * D_SZ / 4) / 256, 256>>>(kp, k1, k2);
    vt_kernel<<<dim3(16, BH_SZ), 128>>>();

    // scores (warp MMA) -> sbuf
    score_kernel<<<dim3(S_SZ / 128, S_SZ / 128, BH_SZ), 256, SCORE_SMEM>>>(mask, sbuf);

    // softmax in place
    softmax_kernel<<<BH_SZ * S_SZ, 256>>>(sbuf);

    // context (warp MMA) -> g_ctx
    ctx_kernel<<<dim3(S_SZ / 128, BH_SZ), 256, CTX_SMEM>>>(sbuf);

    // output projection + LN
    gemm_kernel<<<gemm_grid, 256>>>(ctx, Wo, bo, op, 0);
    ln_kernel<<<M_SZ, 256>>>(Q, gamma, beta, outp);
}

// round 8
// speedup vs baseline: 4.6195x; 1.3776x over previous
#include <cuda_runtime.h>
#include <cuda_bf16.h>
#include <cstdint>

// ---------------------------------------------------------------------------
// Problem constants
// ---------------------------------------------------------------------------
#define B_SZ 2
#define S_SZ 2048
#define D_SZ 1024
#define H_SZ 16
#define DK_SZ 64
#define BH_SZ (B_SZ * H_SZ)                   // 32
#define M_SZ (B_SZ * S_SZ)                    // 4096
#define OUT_ELEMS (B_SZ * S_SZ * D_SZ)        // 4,194,304
#define ATTN_ELEMS (134217728)                // B*H*S*S

// ---------------------------------------------------------------------------
// Scratch
// ---------------------------------------------------------------------------
__device__ float g_v[M_SZ * D_SZ];            // v proj fp32 [bh,s,dv]
__device__ float g_ctx[M_SZ * D_SZ];          // [b,s,h*dv]
__device__ float g_o[M_SZ * D_SZ];
__device__ __nv_bfloat16 g_a1[M_SZ * D_SZ];   // GEMM activation splits
__device__ __nv_bfloat16 g_a2[M_SZ * D_SZ];
__device__ __nv_bfloat16 g_wt1[D_SZ * D_SZ];  // weight^T splits [n][k]
__device__ __nv_bfloat16 g_wt2[D_SZ * D_SZ];
__device__ __nv_bfloat16 g_q1[M_SZ * D_SZ];   // q/k proj bf16 hi/lo [bh,s,dk]
__device__ __nv_bfloat16 g_q2[M_SZ * D_SZ];
__device__ __nv_bfloat16 g_k1[M_SZ * D_SZ];
__device__ __nv_bfloat16 g_k2[M_SZ * D_SZ];
__device__ __nv_bfloat16 g_vt1[M_SZ * D_SZ];  // V transposed: [bh][d][s]
__device__ __nv_bfloat16 g_vt2[M_SZ * D_SZ];
__device__ float g_sc[ATTN_ELEMS];            // score/prob scratch (if !write_attn)

// ---------------------------------------------------------------------------
// Warp MMA helpers (sm_80+ features only)
// ---------------------------------------------------------------------------
__device__ __forceinline__ uint32_t smem_u32(const void* p) {
    uint32_t a;
    asm("{ .reg .u64 t; cvta.to.shared.u64 t, %1; cvt.u32.u64 %0, t; }"
        : "=r"(a) : "l"(p));
    return a;
}

__device__ __forceinline__ void mma_bf16(float* c, const uint32_t* a,
                                         const uint32_t* b) {
    asm volatile(
        "mma.sync.aligned.m16n8k16.row.col.f32.bf16.bf16.f32 "
        "{%0,%1,%2,%3}, {%4,%5,%6,%7}, {%8,%9}, {%0,%1,%2,%3};"
        : "+f"(c[0]), "+f"(c[1]), "+f"(c[2]), "+f"(c[3])
        : "r"(a[0]), "r"(a[1]), "r"(a[2]), "r"(a[3]),
          "r"(b[0]), "r"(b[1]));
}

__device__ __forceinline__ void ldsm_x4(uint32_t* r, uint32_t addr) {
    asm volatile("ldmatrix.sync.aligned.m8n8.x4.shared.b16 {%0,%1,%2,%3}, [%4];"
                 : "=r"(r[0]), "=r"(r[1]), "=r"(r[2]), "=r"(r[3]) : "r"(addr));
}
__device__ __forceinline__ void ldsm_x2(uint32_t* r, uint32_t addr) {
    asm volatile("ldmatrix.sync.aligned.m8n8.x2.shared.b16 {%0,%1}, [%2];"
                 : "=r"(r[0]), "=r"(r[1]) : "r"(addr));
}

__device__ __forceinline__ uint32_t bf2pack(__nv_bfloat16 a, __nv_bfloat16 b) {
    __nv_bfloat162 v = {a, b};
    return *reinterpret_cast<uint32_t*>(&v);
}

// Tile stride: 72 bf16 per row (144 B, conflict-staggered, 16B aligned)
#define TSTR 72

// ---------------------------------------------------------------------------
// fp32 -> bf16 hi/lo split (elementwise)
// ---------------------------------------------------------------------------
__global__ void __launch_bounds__(256) split_kernel(
    const float* __restrict__ in, __nv_bfloat16* __restrict__ hi,
    __nv_bfloat16* __restrict__ lo)
{
    const int i = blockIdx.x * 256 + threadIdx.x;
    const float4 v = reinterpret_cast<const float4*>(in)[i];
    __nv_bfloat16 h0 = __float2bfloat16(v.x);
    __nv_bfloat16 h1 = __float2bfloat16(v.y);
    __nv_bfloat16 h2 = __float2bfloat16(v.z);
    __nv_bfloat16 h3 = __float2bfloat16(v.w);
    __nv_bfloat162 H0 = {h0, h1}, H1 = {h2, h3};
    __nv_bfloat162 L0 = {__float2bfloat16(v.x - __bfloat162float(h0)),
                         __float2bfloat16(v.y - __bfloat162float(h1))};
    __nv_bfloat162 L1 = {__float2bfloat16(v.z - __bfloat162float(h2)),
                         __float2bfloat16(v.w - __bfloat162float(h3))};
    reinterpret_cast<__nv_bfloat162*>(hi)[i * 2]     = H0;
    reinterpret_cast<__nv_bfloat162*>(hi)[i * 2 + 1] = H1;
    reinterpret_cast<__nv_bfloat162*>(lo)[i * 2]     = L0;
    reinterpret_cast<__nv_bfloat162*>(lo)[i * 2 + 1] = L1;
}

// ---------------------------------------------------------------------------
// Weight transpose + split: W [k][n] fp32 -> Wt hi/lo [n][k] bf16
// 64x64 tiles, 256 threads.
// ---------------------------------------------------------------------------
__global__ void __launch_bounds__(256) wt_kernel(
    const float* __restrict__ W, __nv_bfloat16* __restrict__ wt1,
    __nv_bfloat16* __restrict__ wt2)
{
    __shared__ float vs[64][65];
    const int k0 = blockIdx.y * 64;
    const int n0 = blockIdx.x * 64;
    const int t  = threadIdx.x;

    for (int i = t; i < 64 * 16; i += 256) {
        const int r = i >> 4, c = i & 15;
        const float4 v = *reinterpret_cast<const float4*>(
            W + (size_t)(k0 + r) * D_SZ + n0 + c * 4);
        vs[r][c * 4 + 0] = v.x; vs[r][c * 4 + 1] = v.y;
        vs[r][c * 4 + 2] = v.z; vs[r][c * 4 + 3] = v.w;
    }
    __syncthreads();

    for (int i = t; i < 64 * 64; i += 256) {
        const int n = i >> 6, k = i & 63;
        const float x = vs[k][n];
        const __nv_bfloat16 h = __float2bfloat16(x);
        const __nv_bfloat16 l = __float2bfloat16(x - __bfloat162float(h));
        const size_t o = (size_t)(n0 + n) * D_SZ + k0 + k;
        wt1[o] = h;
        wt2[o] = l;
    }
}

// ---------------------------------------------------------------------------
// bf16x3 warp-MMA GEMM: C[M,1024] = A @ W + bias
// A: pre-split hi/lo [m][k]; W: pre-split transposed hi/lo [n][k].
// CTA = 128m x 128n, 8 warps (wq in m, wk in n), K looped in 16 chunks of 64.
//   mode 0: fp32 row-major -> outf
//   mode 1: bf16 hi/lo split -> outh/outl at [bh,s,64] layout
//   mode 2: fp32 -> outf at [bh,s,64] layout
// ---------------------------------------------------------------------------
#define GM_A1 0
#define GM_A2 (128 * TSTR)
#define GM_W1 (2 * 128 * TSTR)
#define GM_W2 (3 * 128 * TSTR)
#define GEMM_SMEM (4 * 128 * TSTR * 2)        // 73728 B

__global__ void __launch_bounds__(256) gemm_mma(
    const __nv_bfloat16* __restrict__ a1, const __nv_bfloat16* __restrict__ a2,
    const __nv_bfloat16* __restrict__ wt1, const __nv_bfloat16* __restrict__ wt2,
    const float* __restrict__ bias,
    float* __restrict__ outf, __nv_bfloat16* __restrict__ outh,
    __nv_bfloat16* __restrict__ outl, int mode)
{
    extern __shared__ __align__(16) __nv_bfloat16 sm[];
    const int t = threadIdx.x;
    const int lane = t & 31, wid = t >> 5;
    const int wq = wid & 3, wk = wid >> 2;    // 4 m-warps x 2 n-warps
    const int n0 = blockIdx.x * 128;
    const int m0 = blockIdx.y * 128;
    const uint32_t sb = smem_u32(sm);

    float acc[2][8][4] = {};

    for (int ck = 0; ck < 16; ck++) {
        const int j0 = ck * 64;
        __syncthreads();
        for (int i = t; i < 1024; i += 256) {
            const int r = i >> 3, c = i & 7;
            const int off = r * TSTR + c * 8;
            const size_t ga = (size_t)(m0 + r) * D_SZ + j0 + c * 8;
            const size_t gw = (size_t)(n0 + r) * D_SZ + j0 + c * 8;
            *reinterpret_cast<uint4*>(
                reinterpret_cast<char*>(sm) + (size_t)(GM_A1 + off) * 2) =
                *reinterpret_cast<const uint4*>(a1 + ga);
            *reinterpret_cast<uint4*>(
                reinterpret_cast<char*>(sm) + (size_t)(GM_A2 + off) * 2) =
                *reinterpret_cast<const uint4*>(a2 + ga);
            *reinterpret_cast<uint4*>(
                reinterpret_cast<char*>(sm) + (size_t)(GM_W1 + off) * 2) =
                *reinterpret_cast<const uint4*>(wt1 + gw);
            *reinterpret_cast<uint4*>(
                reinterpret_cast<char*>(sm) + (size_t)(GM_W2 + off) * 2) =
                *reinterpret_cast<const uint4*>(wt2 + gw);
        }
        __syncthreads();

#pragma unroll
        for (int ks = 0; ks < 4; ks++) {
            const int kc = ks * 16;
            uint32_t ah[2][4], al[2][4];
#pragma unroll
            for (int mi = 0; mi < 2; mi++) {
                const int row = wq * 32 + mi * 16 + (lane & 15);
                const int col = kc + ((lane >> 4) << 3);
                ldsm_x4(ah[mi], sb + (uint32_t)(GM_A1 + row * TSTR + col) * 2);
                ldsm_x4(al[mi], sb + (uint32_t)(GM_A2 + row * TSTR + col) * 2);
            }
#pragma unroll
            for (int ni = 0; ni < 8; ni++) {
                uint32_t bh_[2], bl_[2];
                const int row = wk * 64 + ni * 8 + (lane & 7);
                const int col = kc + (((lane >> 3) & 1) << 3);
                ldsm_x2(bh_, sb + (uint32_t)(GM_W1 + row * TSTR + col) * 2);
                ldsm_x2(bl_, sb + (uint32_t)(GM_W2 + row * TSTR + col) * 2);
#pragma unroll
                for (int mi = 0; mi < 2; mi++) {
                    mma_bf16(acc[mi][ni], ah[mi], bh_);
                    mma_bf16(acc[mi][ni], ah[mi], bl_);
                    mma_bf16(acc[mi][ni], al[mi], bh_);
                }
            }
        }
    }

    // epilogue
    const int g  = lane >> 2;
    const int tg = lane & 3;
#pragma unroll
    for (int mi = 0; mi < 2; mi++) {
#pragma unroll
        for (int ni = 0; ni < 8; ni++) {
            const int col = n0 + wk * 64 + ni * 8 + tg * 2;
            const float2 bb = *reinterpret_cast<const float2*>(bias + col);
            const int m = m0 + wq * 32 + mi * 16 + g;
            float2 r0 = make_float2(acc[mi][ni][0] + bb.x, acc[mi][ni][1] + bb.y);
            float2 r1 = make_float2(acc[mi][ni][2] + bb.x, acc[mi][ni][3] + bb.y);
            if (mode == 0) {
                *reinterpret_cast<float2*>(outf + (size_t)m * D_SZ + col) = r0;
                *reinterpret_cast<float2*>(outf + (size_t)(m + 8) * D_SZ + col) = r1;
            } else {
                const int h  = col >> 6;
                const int dk = col & 63;
                const int b0 = m >> 11, s0 = m & 2047;
                const int b1 = (m + 8) >> 11, s1 = (m + 8) & 2047;
                const size_t o0 = (((size_t)(b0 * H_SZ + h) * S_SZ + s0) * DK_SZ) + dk;
                const size_t o1 = (((size_t)(b1 * H_SZ + h) * S_SZ + s1) * DK_SZ) + dk;
                if (mode == 2) {
                    *reinterpret_cast<float2*>(outf + o0) = r0;
                    *reinterpret_cast<float2*>(outf + o1) = r1;
                } else {
                    const __nv_bfloat16 h00 = __float2bfloat16(r0.x);
                    const __nv_bfloat16 h01 = __float2bfloat16(r0.y);
                    const __nv_bfloat16 h10 = __float2bfloat16(r1.x);
                    const __nv_bfloat16 h11 = __float2bfloat16(r1.y);
                    *reinterpret_cast<uint32_t*>(outh + o0) = bf2pack(h00, h01);
                    *reinterpret_cast<uint32_t*>(outh + o1) = bf2pack(h10, h11);
                    *reinterpret_cast<uint32_t*>(outl + o0) = bf2pack(
                        __float2bfloat16(r0.x - __bfloat162float(h00)),
                        __float2bfloat16(r0.y - __bfloat162float(h01)));
                    *reinterpret_cast<uint32_t*>(outl + o1) = bf2pack(
                        __float2bfloat16(r1.x - __bfloat162float(h10)),
                        __float2bfloat16(r1.y - __bfloat162float(h11)));
                }
            }
        }
    }
}

// ---------------------------------------------------------------------------
// V transpose + split: g_v [bh][s][64] -> g_vt1/2 [bh][64][2048]
// ---------------------------------------------------------------------------
__global__ void __launch_bounds__(128) vt_kernel()
{
    __shared__ float vs[128][65];
    const int jt = blockIdx.x;            // 0..15
    const int bh = blockIdx.y;            // 0..31
    const int t  = threadIdx.x;
    const int j0 = jt * 128;

    const float4* src = reinterpret_cast<const float4*>(
        g_v + ((size_t)bh * S_SZ + j0) * DK_SZ);
    for (int i = t; i < 128 * 16; i += 128) {
        const int r = i >> 4, c = i & 15;
        const float4 v = src[i];
        vs[r][c * 4 + 0] = v.x; vs[r][c * 4 + 1] = v.y;
        vs[r][c * 4 + 2] = v.z; vs[r][c * 4 + 3] = v.w;
    }
    __syncthreads();

    for (int i = t; i < 64 * 128; i += 128) {
        const int j = i & 127;
        const int d = i >> 7;
        const float x = vs[j][d];
        const __nv_bfloat16 h = __float2bfloat16(x);
        const __nv_bfloat16 l = __float2bfloat16(x - __bfloat162float(h));
        const size_t o = ((size_t)bh * 64 + d) * S_SZ + j0 + j;
        g_vt1[o] = h;
        g_vt2[o] = l;
    }
}

// ---------------------------------------------------------------------------
// Score kernel (warp MMA, bf16x3): CTA = 128q x 128k, 8 warps
// ---------------------------------------------------------------------------
#define SQ_H 0
#define SQ_L (128 * TSTR)
#define SK_H (2 * 128 * TSTR)
#define SK_L (3 * 128 * TSTR)
#define SCORE_SMEM (4 * 128 * TSTR * 2)       // 73728 B

__global__ void __launch_bounds__(256) score_kernel(
    const int* __restrict__ mask, float* __restrict__ sbuf)
{
    extern __shared__ __align__(16) __nv_bfloat16 sm[];
    const int t = threadIdx.x;
    const int lane = t & 31, wid = t >> 5;
    const int wq = wid & 3, wk = wid >> 2;
    const int q0 = blockIdx.x * 128, k0 = blockIdx.y * 128;
    const int bh = blockIdx.z, b = bh >> 4;

    {
        const uint4* q1 = reinterpret_cast<const uint4*>(
            g_q1 + ((size_t)bh * S_SZ + q0) * DK_SZ);
        const uint4* q2 = reinterpret_cast<const uint4*>(
            g_q2 + ((size_t)bh * S_SZ + q0) * DK_SZ);
        const uint4* k1 = reinterpret_cast<const uint4*>(
            g_k1 + ((size_t)bh * S_SZ + k0) * DK_SZ);
        const uint4* k2 = reinterpret_cast<const uint4*>(
            g_k2 + ((size_t)bh * S_SZ + k0) * DK_SZ);
        for (int i = t; i < 1024; i += 256) {
            const int r = i >> 3, c = i & 7;
            const int off = r * TSTR + c * 8;
            *reinterpret_cast<uint4*>(
                reinterpret_cast<char*>(sm) + (size_t)(SQ_H + off) * 2) = q1[i];
            *reinterpret_cast<uint4*>(
                reinterpret_cast<char*>(sm) + (size_t)(SQ_L + off) * 2) = q2[i];
            *reinterpret_cast<uint4*>(
                reinterpret_cast<char*>(sm) + (size_t)(SK_H + off) * 2) = k1[i];
            *reinterpret_cast<uint4*>(
                reinterpret_cast<char*>(sm) + (size_t)(SK_L + off) * 2) = k2[i];
        }
    }
    __syncthreads();

    const uint32_t sb = smem_u32(sm);
    float acc[2][8][4] = {};

#pragma unroll
    for (int ks = 0; ks < 4; ks++) {
        const int kc = ks * 16;
        uint32_t ah[2][4], al[2][4];
#pragma unroll
        for (int mi = 0; mi < 2; mi++) {
            const int row = wq * 32 + mi * 16 + (lane & 15);
            const int col = kc + ((lane >> 4) << 3);
            ldsm_x4(ah[mi], sb + (uint32_t)(SQ_H + row * TSTR + col) * 2);
            ldsm_x4(al[mi], sb + (uint32_t)(SQ_L + row * TSTR + col) * 2);
        }
#pragma unroll
        for (int ni = 0; ni < 8; ni++) {
            uint32_t bh_[2], bl_[2];
            const int row = wk * 64 + ni * 8 + (lane & 7);
            const int col = kc + (((lane >> 3) & 1) << 3);
            ldsm_x2(bh_, sb + (uint32_t)(SK_H + row * TSTR + col) * 2);
            ldsm_x2(bl_, sb + (uint32_t)(SK_L + row * TSTR + col) * 2);
#pragma unroll
            for (int mi = 0; mi < 2; mi++) {
                mma_bf16(acc[mi][ni], ah[mi], bh_);
                mma_bf16(acc[mi][ni], ah[mi], bl_);
                mma_bf16(acc[mi][ni], al[mi], bh_);
            }
        }
    }

    const int g  = lane >> 2;
    const int tg = lane & 3;
#pragma unroll
    for (int mi = 0; mi < 2; mi++) {
#pragma unroll
        for (int ni = 0; ni < 8; ni++) {
            const int q = q0 + wq * 32 + mi * 16 + g;
            const int k = k0 + wk * 64 + ni * 8 + tg * 2;
            const int2 m0 = *reinterpret_cast<const int2*>(
                mask + ((size_t)b * S_SZ + q) * S_SZ + k);
            const int2 m1 = *reinterpret_cast<const int2*>(
                mask + ((size_t)b * S_SZ + q + 8) * S_SZ + k);
            float2 s0, s1;
            s0.x = m0.x ? -1e9f : acc[mi][ni][0] * 0.125f;
            s0.y = m0.y ? -1e9f : acc[mi][ni][1] * 0.125f;
            s1.x = m1.x ? -1e9f : acc[mi][ni][2] * 0.125f;
            s1.y = m1.y ? -1e9f : acc[mi][ni][3] * 0.125f;
            *reinterpret_cast<float2*>(
                sbuf + ((size_t)bh * S_SZ + q) * S_SZ + k) = s0;
            *reinterpret_cast<float2*>(
                sbuf + ((size_t)bh * S_SZ + q + 8) * S_SZ + k) = s1;
        }
    }
}

// ---------------------------------------------------------------------------
// Softmax (in place over rows of 2048)
// ---------------------------------------------------------------------------
__global__ void __launch_bounds__(256) softmax_kernel(float* __restrict__ buf)
{
    __shared__ float red[8];
    const size_t row = blockIdx.x;
    const int t = threadIdx.x;
    float4* p4 = reinterpret_cast<float4*>(buf + row * S_SZ);

    float4 v0 = p4[t], v1 = p4[t + 256];
    float mx = fmaxf(fmaxf(fmaxf(v0.x, v0.y), fmaxf(v0.z, v0.w)),
                     fmaxf(fmaxf(v1.x, v1.y), fmaxf(v1.z, v1.w)));
#pragma unroll
    for (int o = 16; o; o >>= 1) mx = fmaxf(mx, __shfl_xor_sync(0xffffffffu, mx, o));
    if ((t & 31) == 0) red[t >> 5] = mx;
    __syncthreads();
    mx = fmaxf(fmaxf(fmaxf(red[0], red[1]), fmaxf(red[2], red[3])),
               fmaxf(fmaxf(red[4], red[5]), fmaxf(red[6], red[7])));
    __syncthreads();

    v0.x = __expf(v0.x - mx); v0.y = __expf(v0.y - mx);
    v0.z = __expf(v0.z - mx); v0.w = __expf(v0.w - mx);
    v1.x = __expf(v1.x - mx); v1.y = __expf(v1.y - mx);
    v1.z = __expf(v1.z - mx); v1.w = __expf(v1.w - mx);
    float sum = v0.x + v0.y + v0.z + v0.w + v1.x + v1.y + v1.z + v1.w;
#pragma unroll
    for (int o = 16; o; o >>= 1) sum += __shfl_xor_sync(0xffffffffu, sum, o);
    if ((t & 31) == 0) red[t >> 5] = sum;
    __syncthreads();
    const float inv = 1.f / (red[0] + red[1] + red[2] + red[3] +
                             red[4] + red[5] + red[6] + red[7]);

    v0.x *= inv; v0.y *= inv; v0.z *= inv; v0.w *= inv;
    v1.x *= inv; v1.y *= inv; v1.z *= inv; v1.w *= inv;
    p4[t] = v0;
    p4[t + 256] = v1;
}

// ---------------------------------------------------------------------------
// Context kernel (warp MMA, bf16x3): CTA = 128q x 64d, K=2048 in 32 chunks.
// ---------------------------------------------------------------------------
#define CP_H 0
#define CP_L (128 * TSTR)
#define CV_H (2 * 128 * TSTR)
#define CV_L (2 * 128 * TSTR + 64 * TSTR)
#define CTX_SMEM ((2 * 128 * TSTR + 2 * 64 * TSTR) * 2)   // 55296 B

__global__ void __launch_bounds__(256) ctx_kernel(const float* __restrict__ probs)
{
    extern __shared__ __align__(16) __nv_bfloat16 sm[];
    const int t = threadIdx.x;
    const int lane = t & 31, wid = t >> 5;
    const int q0 = blockIdx.x * 128;
    const int bh = blockIdx.y, b = bh >> 4, h = bh & 15;
    const uint32_t sb = smem_u32(sm);

    const float* prow = probs + ((size_t)bh * S_SZ + q0) * S_SZ;
    const __nv_bfloat16* vt1 = g_vt1 + (size_t)bh * 64 * S_SZ;
    const __nv_bfloat16* vt2 = g_vt2 + (size_t)bh * 64 * S_SZ;

    float acc[8][4] = {};

    for (int ch = 0; ch < 32; ch++) {
        const int j0 = ch * 64;
        __syncthreads();
        for (int i = t; i < 2048; i += 256) {
            const int r = i >> 4, c = i & 15;
            const float4 v = *reinterpret_cast<const float4*>(
                prow + (size_t)r * S_SZ + j0 + c * 4);
            const __nv_bfloat16 h0 = __float2bfloat16(v.x);
            const __nv_bfloat16 h1 = __float2bfloat16(v.y);
            const __nv_bfloat16 h2 = __float2bfloat16(v.z);
            const __nv_bfloat16 h3 = __float2bfloat16(v.w);
            const uint2 hp = make_uint2(bf2pack(h0, h1), bf2pack(h2, h3));
            const uint2 lp = make_uint2(
                bf2pack(__float2bfloat16(v.x - __bfloat162float(h0)),
                        __float2bfloat16(v.y - __bfloat162float(h1))),
                bf2pack(__float2bfloat16(v.z - __bfloat162float(h2)),
                        __float2bfloat16(v.w - __bfloat162float(h3))));
            const int off = r * TSTR + c * 4;
            *reinterpret_cast<uint2*>(
                reinterpret_cast<char*>(sm) + (size_t)(CP_H + off) * 2) = hp;
            *reinterpret_cast<uint2*>(
                reinterpret_cast<char*>(sm) + (size_t)(CP_L + off) * 2) = lp;
        }
        for (int i = t; i < 512; i += 256) {
            const int r = i >> 3, c = i & 7;
            const int off = r * TSTR + c * 8;
            *reinterpret_cast<uint4*>(
                reinterpret_cast<char*>(sm) + (size_t)(CV_H + off) * 2) =
                *reinterpret_cast<const uint4*>(vt1 + (size_t)r * S_SZ + j0 + c * 8);
            *reinterpret_cast<uint4*>(
                reinterpret_cast<char*>(sm) + (size_t)(CV_L + off) * 2) =
                *reinterpret_cast<const uint4*>(vt2 + (size_t)r * S_SZ + j0 + c * 8);
        }
        __syncthreads();

#pragma unroll
        for (int ks = 0; ks < 4; ks++) {
            const int kc = ks * 16;
            uint32_t ah[4], al[4];
            {
                const int row = wid * 16 + (lane & 15);
                const int col = kc + ((lane >> 4) << 3);
                ldsm_x4(ah, sb + (uint32_t)(CP_H + row * TSTR + col) * 2);
                ldsm_x4(al, sb + (uint32_t)(CP_L + row * TSTR + col) * 2);
            }
#pragma unroll
            for (int ni = 0; ni < 8; ni++) {
                uint32_t bh_[2], bl_[2];
                const int row = ni * 8 + (lane & 7);
                const int col = kc + (((lane >> 3) & 1) << 3);
                ldsm_x2(bh_, sb + (uint32_t)(CV_H + row * TSTR + col) * 2);
                ldsm_x2(bl_, sb + (uint32_t)(CV_L + row * TSTR + col) * 2);
                mma_bf16(acc[ni], ah, bh_);
                mma_bf16(acc[ni], ah, bl_);
                mma_bf16(acc[ni], al, bh_);
            }
        }
    }

    const int g  = lane >> 2;
    const int tg = lane & 3;
#pragma unroll
    for (int ni = 0; ni < 8; ni++) {
        const int q = q0 + wid * 16 + g;
        const int d = ni * 8 + tg * 2;
        *reinterpret_cast<float2*>(
            g_ctx + ((size_t)(b * S_SZ + q)) * D_SZ + h * DK_SZ + d) =
            make_float2(acc[ni][0], acc[ni][1]);
        *reinterpret_cast<float2*>(
            g_ctx + ((size_t)(b * S_SZ + q + 8)) * D_SZ + h * DK_SZ + d) =
            make_float2(acc[ni][2], acc[ni][3]);
    }
}

// ---------------------------------------------------------------------------
// Residual + LayerNorm
// ---------------------------------------------------------------------------
__global__ void __launch_bounds__(256) ln_kernel(
    const float* __restrict__ resid, const float* __restrict__ gamma,
    const float* __restrict__ beta, float* __restrict__ out)
{
    __shared__ float rs[8], rq[8];
    const int row = blockIdx.x;
    const int t = threadIdx.x;

    const float4 a = reinterpret_cast<const float4*>(g_o + (size_t)row * D_SZ)[t];
    const float4 r = reinterpret_cast<const float4*>(resid + (size_t)row * D_SZ)[t];
    const float4 v = make_float4(a.x + r.x, a.y + r.y, a.z + r.z, a.w + r.w);

    float s  = v.x + v.y + v.z + v.w;
    float sq = v.x * v.x + v.y * v.y + v.z * v.z + v.w * v.w;
#pragma unroll
    for (int o = 16; o; o >>= 1) {
        s  += __shfl_xor_sync(0xffffffffu, s, o);
        sq += __shfl_xor_sync(0xffffffffu, sq, o);
    }
    if ((t & 31) == 0) { rs[t >> 5] = s; rq[t >> 5] = sq; }
    __syncthreads();
    float S = 0.f, SQ = 0.f;
#pragma unroll
    for (int i = 0; i < 8; i++) { S += rs[i]; SQ += rq[i]; }
    const float mu  = S * (1.f / D_SZ);
    const float var = SQ * (1.f / D_SZ) - mu * mu;
    const float rstd = rsqrtf(var + 1e-5f);

    const float4 g  = reinterpret_cast<const float4*>(gamma)[t];
    const float4 be = reinterpret_cast<const float4*>(beta)[t];
    reinterpret_cast<float4*>(out + (size_t)row * D_SZ)[t] =
        make_float4((v.x - mu) * rstd * g.x + be.x,
                    (v.y - mu) * rstd * g.y + be.y,
                    (v.z - mu) * rstd * g.z + be.z,
                    (v.w - mu) * rstd * g.w + be.w);
}

// ---------------------------------------------------------------------------
// kernel_launch
// ---------------------------------------------------------------------------
extern "C" void kernel_launch(void* const* d_in, const int* in_sizes, int n_in,
                              void* d_out, int out_size)
{
    const float* Q  = (const float*)d_in[0];
    const float* K  = (const float*)d_in[1];
    const float* V  = (const float*)d_in[2];
    const int*   mask = (const int*)d_in[3];
    const float* Wq = (const float*)d_in[4];
    const float* bq = (const float*)d_in[5];
    const float* Wk = (const float*)d_in[6];
    const float* bk = (const float*)d_in[7];
    const float* Wv = (const float*)d_in[8];
    const float* bv = (const float*)d_in[9];
    const float* Wo = (const float*)d_in[10];
    const float* bo = (const float*)d_in[11];
    const float* gamma = (const float*)d_in[12];
    const float* beta  = (const float*)d_in[13];

    float *vp, *ctx, *op, *scp;
    __nv_bfloat16 *a1, *a2, *w1, *w2, *q1, *q2, *k1, *k2;
    cudaGetSymbolAddress((void**)&vp,  g_v);
    cudaGetSymbolAddress((void**)&ctx, g_ctx);
    cudaGetSymbolAddress((void**)&op,  g_o);
    cudaGetSymbolAddress((void**)&scp, g_sc);
    cudaGetSymbolAddress((void**)&a1,  g_a1);
    cudaGetSymbolAddress((void**)&a2,  g_a2);
    cudaGetSymbolAddress((void**)&w1,  g_wt1);
    cudaGetSymbolAddress((void**)&w2,  g_wt2);
    cudaGetSymbolAddress((void**)&q1,  g_q1);
    cudaGetSymbolAddress((void**)&q2,  g_q2);
    cudaGetSymbolAddress((void**)&k1,  g_k1);
    cudaGetSymbolAddress((void**)&k2,  g_k2);

    float* outp = (float*)d_out;
    float* sbuf = scp;
    if ((long long)out_size >= (long long)OUT_ELEMS + (long long)ATTN_ELEMS)
        sbuf = outp + OUT_ELEMS;   // probs land directly in the attn output

    cudaFuncSetAttribute(score_kernel,
        cudaFuncAttributeMaxDynamicSharedMemorySize, SCORE_SMEM);
    cudaFuncSetAttribute(ctx_kernel,
        cudaFuncAttributeMaxDynamicSharedMemorySize, CTX_SMEM);
    cudaFuncSetAttribute(gemm_mma,
        cudaFuncAttributeMaxDynamicSharedMemorySize, GEMM_SMEM);

    const dim3 wt_grid(D_SZ / 64, D_SZ / 64);          // (16,16)
    const dim3 gm_grid(D_SZ / 128, M_SZ / 128);        // (8, 32)
    const int  split_blocks = (M_SZ * D_SZ / 4) / 256; // 4096

    // q projection: split A, transpose W, GEMM -> q hi/lo (split fused)
    split_kernel<<<split_blocks, 256>>>(Q, a1, a2);
    wt_kernel<<<wt_grid, 256>>>(Wq, w1, w2);
    gemm_mma<<<gm_grid, 256, GEMM_SMEM>>>(a1, a2, w1, w2, bq, nullptr, q1, q2, 1);

    // k projection
    split_kernel<<<split_blocks, 256>>>(K, a1, a2);
    wt_kernel<<<wt_grid, 256>>>(Wk, w1, w2);
    gemm_mma<<<gm_grid, 256, GEMM_SMEM>>>(a1, a2, w1, w2, bk, nullptr, k1, k2, 1);

    // v projection -> fp32 [bh,s,64], then transpose+split
    split_kernel<<<split_blocks, 256>>>(V, a1, a2);
    wt_kernel<<<wt_grid, 256>>>(Wv, w1, w2);
    gemm_mma<<<gm_grid, 256, GEMM_SMEM>>>(a1, a2, w1, w2, bv, vp, nullptr, nullptr, 2);
    vt_kernel<<<dim3(16, BH_SZ), 128>>>();

    // attention
    score_kernel<<<dim3(S_SZ / 128, S_SZ / 128, BH_SZ), 256, SCORE_SMEM>>>(mask, sbuf);
    softmax_kernel<<<BH_SZ * S_SZ, 256>>>(sbuf);
    ctx_kernel<<<dim3(S_SZ / 128, BH_SZ), 256, CTX_SMEM>>>(sbuf);

    // output projection (ctx @ Wo + bo) -> g_o
    split_kernel<<<split_blocks, 256>>>(ctx, a1, a2);
    wt_kernel<<<wt_grid, 256>>>(Wo, w1, w2);
    gemm_mma<<<gm_grid, 256, GEMM_SMEM>>>(a1, a2, w1, w2, bo, op, nullptr, nullptr, 0);

    // residual + layernorm
    ln_kernel<<<M_SZ, 256>>>(Q, gamma, beta, outp);
}